// round 2
// baseline (speedup 1.0000x reference)
#include <cuda_runtime.h>

// out = inputs * (noise >= 0.5f ? 2.0f : 0.0f)
// 67,108,864 fp32 = 16,777,216 float4 = 16384 blocks * 256 threads * 4 vec4/thread.
// Pure streaming: front-batched LDG.128 x8 per thread (MLP=8), streaming cache
// hints (evict-first) since every byte is touched exactly once.

#define VPT 4  // float4 per thread per array

__global__ void __launch_bounds__(256)
sparse_dropout_vec4x4(const float4* __restrict__ inputs,
                      const float4* __restrict__ noise,
                      float4* __restrict__ out)
{
    const unsigned base = (blockIdx.x * blockDim.x) * VPT + threadIdx.x;

    float4 x[VPT];
    float4 n[VPT];

    // Front-batch all loads (independent, coalesced: stride blockDim between chunks)
#pragma unroll
    for (int k = 0; k < VPT; k++)
        x[k] = __ldcs(&inputs[base + k * 256]);
#pragma unroll
    for (int k = 0; k < VPT; k++)
        n[k] = __ldcs(&noise[base + k * 256]);

#pragma unroll
    for (int k = 0; k < VPT; k++) {
        float4 r;
        r.x = (n[k].x >= 0.5f) ? x[k].x * 2.0f : 0.0f;
        r.y = (n[k].y >= 0.5f) ? x[k].y * 2.0f : 0.0f;
        r.z = (n[k].z >= 0.5f) ? x[k].z * 2.0f : 0.0f;
        r.w = (n[k].w >= 0.5f) ? x[k].w * 2.0f : 0.0f;
        __stcs(&out[base + k * 256], r);
    }
}

extern "C" void kernel_launch(void* const* d_in, const int* in_sizes, int n_in,
                              void* d_out, int out_size)
{
    const float4* inputs = (const float4*)d_in[0];
    const float4* noise  = (const float4*)d_in[1];
    float4* out          = (float4*)d_out;

    const int n_vec4 = out_size / 4;            // 16,777,216
    const int threads = 256;
    const int blocks = n_vec4 / (threads * VPT); // 16384, exact

    sparse_dropout_vec4x4<<<blocks, threads>>>(inputs, noise, out);
}